// round 5
// baseline (speedup 1.0000x reference)
#include <cuda_runtime.h>

#define SIDE   32
#define UNITS  1024
#define BATCH  128
#define TSTEPS 512
#define NT     256
#define MDW    34   // Md row stride in ulls (32 + 2 pad)

typedef unsigned long long ull;

#define FMA2(acc, a, m)    asm("fma.rn.f32x2 %0, %1, %2, %0;" : "+l"(acc) : "l"(a), "l"(m))
#define FADD2(d, a, b)     asm("add.rn.f32x2 %0, %1, %2;" : "=l"(d) : "l"(a), "l"(b))
#define PACK2(d, lo, hi)   asm("mov.b64 %0, {%1, %2};" : "=l"(d) : "f"(lo), "f"(hi))
#define UNPACK2(lo, hi, s) asm("mov.b64 {%0, %1}, %2;" : "=f"(lo), "=f"(hi) : "l"(s))

__global__ __launch_bounds__(NT, 1)
void minrnn_kernel(const float* __restrict__ x, const float* __restrict__ b,
                   const float* __restrict__ b2, const float* __restrict__ h0,
                   float* __restrict__ out)
{
    // At[buf][j][r] = A[r][j]  (A^T, 128B rows; loads & stores at wf-minimum)
    __shared__ __align__(16) float At[2][SIDE][SIDE];
    // Md[buf][j][c] = {M[j][c], M[j][c]} duplicated for FFMA2
    __shared__ __align__(16) ull   Md[2][SIDE][MDW];
    // partial exchange, chunk-major: lanes write/read consecutive 16B
    __shared__ __align__(16) ulonglong2 Psh[2][128];

    const int tid = threadIdx.x;
    const int bb  = blockIdx.x;
    const int pos = tid & 127;       // tile position
    const int jh  = tid >> 7;        // j-half: 0 -> j 0..15 (+reduce), 1 -> j 16..31 (+M fill)
    const int rg  = pos & 7;         // row quad
    const int cg  = pos >> 3;        // col pair (0..15)
    const int r0  = rg * 4;
    const int c0  = cg * 2;          // column index == ull index into Md row
    const int jb  = jh * 16;

    // ---- jh=0 constants: b2 packs b2p[p][cc] = {b2[r0+2p][c0+cc], b2[r0+2p+1][c0+cc]} ----
    ull b2p[2][2];
    if (jh == 0) {
#pragma unroll
        for (int p = 0; p < 2; p++)
#pragma unroll
            for (int cc = 0; cc < 2; cc++)
                PACK2(b2p[p][cc], b2[(r0 + 2*p) * SIDE + c0 + cc],
                                  b2[(r0 + 2*p + 1) * SIDE + c0 + cc]);
    }

    // ---- jh=1 constants: M-fill role (8 M entries: row jm, cols cf*8..cf*8+7) ----
    const int jm = pos >> 2;
    const int cf = pos & 3;
    ull bfp[4];
    const float* xbase = x + (size_t)bb * TSTEPS * UNITS + pos * 8;
    ulonglong2 xr[2][2];             // x prefetch ring, depth 2 (32B/thread/step)
    if (jh == 1) {
        const float* bp = b + jm * SIDE + cf * 8;
#pragma unroll
        for (int e = 0; e < 4; e++) PACK2(bfp[e], bp[2*e], bp[2*e + 1]);
#pragma unroll
        for (int s = 0; s < 2; s++) {
            const ulonglong2* p = (const ulonglong2*)(xbase + (size_t)s * UNITS);
            xr[s][0] = p[0]; xr[s][1] = p[1];
        }
    }

    // ---- prologue: buffer 0 ----
    if (jh == 0) {
        const float* hp = h0 + bb * UNITS;
#pragma unroll
        for (int cc = 0; cc < 2; cc++) {
            ull hk, v0, v1;
            PACK2(hk, hp[r0 * SIDE + c0 + cc], hp[(r0 + 1) * SIDE + c0 + cc]);
            FADD2(v0, hk, b2p[0][cc]);
            PACK2(hk, hp[(r0 + 2) * SIDE + c0 + cc], hp[(r0 + 3) * SIDE + c0 + cc]);
            FADD2(v1, hk, b2p[1][cc]);
            ulonglong2 st; st.x = v0; st.y = v1;
            *(ulonglong2*)&At[0][c0 + cc][r0] = st;
        }
    } else {
        const ull xs[4] = { xr[0][0].x, xr[0][0].y, xr[0][1].x, xr[0][1].y };
#pragma unroll
        for (int e = 0; e < 4; e++) {
            ull m, d0, d1; float f0, f1;
            FADD2(m, xs[e], bfp[e]);
            UNPACK2(f0, f1, m);
            PACK2(d0, f0, f0); PACK2(d1, f1, f1);
            ulonglong2 st; st.x = d0; st.y = d1;
            *(ulonglong2*)&Md[0][jm][cf * 8 + 2*e] = st;
        }
    }
    __syncthreads();

#pragma unroll 2
    for (int t = 0; t < TSTEPS; t++) {
        const int pb = t & 1;
        const int nb = pb ^ 1;

        // jh=1: prefetch x(t+2) into freed ring slot
        if (jh == 1 && t + 2 < TSTEPS) {
            const ulonglong2* p = (const ulonglong2*)(xbase + (size_t)(t + 2) * UNITS);
            xr[t & 1][0] = p[0]; xr[t & 1][1] = p[1];
        }

        // ---- j-loop: 16 js, 3-stage modulo software pipeline ----
        ull a00 = 0, a01 = 0, a10 = 0, a11 = 0;
        ulonglong2 sa[3], sm[3];
#pragma unroll
        for (int s = 0; s < 2; s++) {
            sa[s] = *(const ulonglong2*)&At[pb][jb + s][r0];
            sm[s] = *(const ulonglong2*)&Md[pb][jb + s][c0];
        }
#pragma unroll
        for (int jj = 0; jj < 16; jj++) {
            if (jj + 2 < 16) {
                const int s = (jj + 2) % 3;
                sa[s] = *(const ulonglong2*)&At[pb][jb + jj + 2][r0];
                sm[s] = *(const ulonglong2*)&Md[pb][jb + jj + 2][c0];
            }
            const int s = jj % 3;
            FMA2(a00, sa[s].x, sm[s].x);   // rows r0,r0+1  x col c0
            FMA2(a01, sa[s].x, sm[s].y);   // rows r0,r0+1  x col c0+1
            FMA2(a10, sa[s].y, sm[s].x);   // rows r0+2,+3  x col c0
            FMA2(a11, sa[s].y, sm[s].y);   // rows r0+2,+3  x col c0+1
        }

        // jh=1: publish partials (consumed by jh=0 after bar0)
        if (jh == 1) {
            ulonglong2 st;
            st.x = a00; st.y = a01; Psh[0][pos] = st;
            st.x = a10; st.y = a11; Psh[1][pos] = st;
        }
        __syncthreads();   // bar0: buf-pb reads done; partials visible

        if (jh == 0) {
            ulonglong2 q0 = Psh[0][pos];
            ulonglong2 q1 = Psh[1][pos];
            FADD2(a00, a00, q0.x); FADD2(a01, a01, q0.y);
            FADD2(a10, a10, q1.x); FADD2(a11, a11, q1.y);
            if (t + 1 < TSTEPS) {
                // A(t+1) = h + b2 -> At[nb]
                ull v0, v1;
                FADD2(v0, a00, b2p[0][0]); FADD2(v1, a10, b2p[1][0]);
                { ulonglong2 st; st.x = v0; st.y = v1; *(ulonglong2*)&At[nb][c0][r0] = st; }
                FADD2(v0, a01, b2p[0][1]); FADD2(v1, a11, b2p[1][1]);
                { ulonglong2 st; st.x = v0; st.y = v1; *(ulonglong2*)&At[nb][c0 + 1][r0] = st; }
            } else {
                // final h (without b2) -> GMEM
                float l0, u0, l1, u1;
                float* op = out + bb * UNITS;
                UNPACK2(l0, u0, a00); UNPACK2(l1, u1, a01);
                *(float2*)(op + (r0 + 0) * SIDE + c0) = make_float2(l0, l1);
                *(float2*)(op + (r0 + 1) * SIDE + c0) = make_float2(u0, u1);
                UNPACK2(l0, u0, a10); UNPACK2(l1, u1, a11);
                *(float2*)(op + (r0 + 2) * SIDE + c0) = make_float2(l0, l1);
                *(float2*)(op + (r0 + 3) * SIDE + c0) = make_float2(u0, u1);
            }
        } else if (t + 1 < TSTEPS) {
            // M(t+1) = dup(b + x(t+1)) -> Md[nb]
            const int s = (t + 1) & 1;
            const ull xs[4] = { xr[s][0].x, xr[s][0].y, xr[s][1].x, xr[s][1].y };
#pragma unroll
            for (int e = 0; e < 4; e++) {
                ull m, d0, d1; float f0, f1;
                FADD2(m, xs[e], bfp[e]);
                UNPACK2(f0, f1, m);
                PACK2(d0, f0, f0); PACK2(d1, f1, f1);
                ulonglong2 st; st.x = d0; st.y = d1;
                *(ulonglong2*)&Md[nb][jm][cf * 8 + 2*e] = st;
            }
        }
        __syncthreads();   // bar1: buf nb complete
    }
}

extern "C" void kernel_launch(void* const* d_in, const int* in_sizes, int n_in,
                              void* d_out, int out_size)
{
    const float* x  = (const float*)d_in[0];   // [128, 512, 1024]
    const float* b  = (const float*)d_in[1];   // [1024]
    const float* b2 = (const float*)d_in[2];   // [1024]
    const float* h0 = (const float*)d_in[3];   // [128, 1024]
    float* out = (float*)d_out;                // [128, 1024]
    minrnn_kernel<<<BATCH, NT>>>(x, b, b2, h0, out);
}